// round 13
// baseline (speedup 1.0000x reference)
#include <cuda_runtime.h>
#include <math.h>
#include <stdint.h>

// Problem constants
#define B_   32
#define T_   2000
#define DE_  512
#define DD_  1024
#define A_   128
#define FN_  32
#define FS_  16
#define KW_  33

#define TILE_M 64            // t-rows per CTA tile
#define BKF    16            // K floats per chunk (= one m16n8k16 slab)
#define NCHG   32            // gmem K-chunks (512/16)
#define LDS_   24            // padded smem row stride (floats): conflict-free LDS.64
#define SEG_   20
#define TSEG   (T_/SEG_)     // 100

// dynamic smem (float offsets): 4 A bufs (64x24), 4 B bufs (128x24) = 72KB exact
#define ABUF(i)  ((i) * 1536)
#define BBUF(i)  (6144 + (i) * 3072)
#define SPATT_O  4608                     // aliases ABUF(3), used only after mainloop
#define SRED_O   0                        // aliases ABUF(0), used only in epilogue
#define SMEM_FLOATS 18432                 // 73728 bytes = 72 KB

// Scratch (no cudaMalloc allowed)
__device__ float g_eff[KW_ * A_];        // eff[k][a]
__device__ float g_pd[B_ * A_];          // dec projection + att_b
__device__ float g_score[B_ * T_];
__device__ float g_stats[B_ * 2];        // max, 1/sum

__device__ __forceinline__ uint32_t smem_u32(const void* p) {
    uint32_t a;
    asm("{ .reg .u64 t; cvta.to.shared.u64 t, %1; cvt.u32.u64 %0, t; }" : "=r"(a) : "l"(p));
    return a;
}
__device__ __forceinline__ void cp16(uint32_t dst, uint64_t src, int srcsz) {
    asm volatile("cp.async.cg.shared.global [%0], [%1], 16, %2;"
                 :: "r"(dst), "l"(src), "r"(srcsz) : "memory");
}
// load two consecutive k floats, round to fp16 pair {lo=k, hi=k+1}
__device__ __forceinline__ uint32_t packh2(const float* p) {
    float2 v = *(const float2*)p;
    uint32_t r;
    asm("cvt.rn.f16x2.f32 %0, %1, %2;" : "=r"(r) : "f"(v.y), "f"(v.x));
    return r;
}
__device__ __forceinline__ void mma_f16(float* d, const uint32_t* a, const uint32_t* bb) {
    asm volatile(
        "mma.sync.aligned.m16n8k16.row.col.f32.f16.f16.f32 "
        "{%0,%1,%2,%3}, {%4,%5,%6,%7}, {%8,%9}, {%0,%1,%2,%3};"
        : "+f"(d[0]), "+f"(d[1]), "+f"(d[2]), "+f"(d[3])
        : "r"(a[0]), "r"(a[1]), "r"(a[2]), "r"(a[3]), "r"(bb[0]), "r"(bb[1]));
}

// ---------------------------------------------------------------------------
// K0 (idx 0): prep — fold conv through att_w (block 0), decoder projection
//             + att_b (block b), zero ctx accumulators.  grid B_, 128 threads.
// ---------------------------------------------------------------------------
__global__ void k_prep(const float* __restrict__ att_w, const float* __restrict__ conv_w,
                       const float* __restrict__ dec_w, const float* __restrict__ input_dec,
                       const float* __restrict__ att_b, float* __restrict__ ctx_out) {
    __shared__ float sdec[DD_];
    int b = blockIdx.x, tid = threadIdx.x;

#pragma unroll
    for (int i = 0; i < 4; ++i) ctx_out[b * DE_ + i * 128 + tid] = 0.f;

    if (b == 0) {
        int a = tid;
        float aw[FN_];
#pragma unroll
        for (int f = 0; f < FN_; ++f) aw[f] = att_w[a * FN_ + f];
        for (int k = 0; k < KW_; ++k) {
            float s = 0.f;
#pragma unroll
            for (int f = 0; f < FN_; ++f) s = fmaf(aw[f], conv_w[f * KW_ + k], s);
            g_eff[k * A_ + a] = s;
        }
    }

    for (int i = tid; i < DD_; i += blockDim.x) sdec[i] = input_dec[b * DD_ + i];
    __syncthreads();
    const float4* wr = (const float4*)(dec_w + (size_t)tid * DD_);
    const float4* xr = (const float4*)sdec;
    float s = 0.f;
#pragma unroll 4
    for (int i = 0; i < DD_ / 4; ++i) {
        float4 w = wr[i], x = xr[i];
        s = fmaf(w.x, x.x, fmaf(w.y, x.y, fmaf(w.z, x.z, fmaf(w.w, x.w, s))));
    }
    g_pd[b * A_ + tid] = s + att_b[tid];
}

// ---------------------------------------------------------------------------
// K1 (idx 1): fp16 m16n8k16 mma.sync score GEMM (fp32 accum).
//     CTA tile 64(t) x 128(a); 8 warps, warp tile 32x32; 3 CTAs/SM.
//     cp.async 4-buffer depth-3 pipeline; FIR + bias folded as extra K.
// ---------------------------------------------------------------------------
__global__ void __launch_bounds__(256, 3)
k_score(const float* __restrict__ enc, const float* __restrict__ enc_w,
        const float* __restrict__ prev_att, const float* __restrict__ out_w,
        const int* __restrict__ lengths)
{
    extern __shared__ float dsm[];

    const int b     = blockIdx.y;
    const int trow0 = blockIdx.x * TILE_M;
    const int tid   = threadIdx.x;
    const int lane  = tid & 31;
    const int wid   = tid >> 5;
    const int warp_m = wid & 1;      // 2 groups of 32 t-rows
    const int warp_n = wid >> 1;     // 4 groups of 32 a-cols
    const int g     = lane >> 2;
    const int tg    = lane & 3;
    const int r     = tid >> 2;      // loader row 0..63
    const int q     = tid & 3;       // loader quad

    const int len = lengths[b];
    if (trow0 >= len) {              // fully masked tile
        for (int i = tid; i < TILE_M; i += 256) {
            int t = trow0 + i;
            if (t < T_) g_score[b * T_ + t] = -INFINITY;
        }
        return;
    }

    const uint32_t sbase = smem_u32(dsm);
    uint64_t gA, gW;
    {
        const float* Abase = enc + ((size_t)b * T_ + trow0) * DE_;
        asm("cvta.to.global.u64 %0, %1;" : "=l"(gA) : "l"(Abase));
        asm("cvta.to.global.u64 %0, %1;" : "=l"(gW) : "l"(enc_w));
    }
    const int szA = (trow0 + r < T_) ? 16 : 0;
    const uint32_t soff     = (uint32_t)(r * LDS_ + 4 * q) * 4u;
    const uint32_t rowskipB = 64u * LDS_ * 4u;
    const uint64_t goff     = ((size_t)r * DE_ + 4 * q) * 4;
    const uint64_t growskip = (size_t)64 * DE_ * 4;

    auto issue = [&](int c) {
        const int bi = c & 3;
        const uint32_t da = sbase + (uint32_t)ABUF(bi) * 4u + soff;
        const uint32_t db = sbase + (uint32_t)BBUF(bi) * 4u + soff;
        const uint64_t off = goff + (uint64_t)c * (BKF * 4);
        cp16(da,            gA + off,            szA);   // A: 64 rows
        cp16(db,            gW + off,            16);    // B: rows 0..63
        cp16(db + rowskipB, gW + off + growskip, 16);    // B: rows 64..127
        asm volatile("cp.async.commit_group;" ::: "memory");
    };

    float acc[2][4][4];
#pragma unroll
    for (int mi = 0; mi < 2; ++mi)
#pragma unroll
        for (int ni = 0; ni < 4; ++ni)
#pragma unroll
            for (int j = 0; j < 4; ++j) acc[mi][ni][j] = 0.f;

    auto compute = [&](int bi) {
        const float* Ad = dsm + ABUF(bi);
        const float* Bd = dsm + BBUF(bi);
        const int k0 = 2 * tg;
        uint32_t bf[4][2];
#pragma unroll
        for (int ni = 0; ni < 4; ++ni) {
            int nb = warp_n * 32 + ni * 8 + g;
            bf[ni][0] = packh2(Bd + nb * LDS_ + k0);
            bf[ni][1] = packh2(Bd + nb * LDS_ + k0 + 8);
        }
#pragma unroll
        for (int mi = 0; mi < 2; ++mi) {
            int rb = warp_m * 32 + mi * 16 + g;
            uint32_t af[4];
            af[0] = packh2(Ad + rb * LDS_ + k0);
            af[1] = packh2(Ad + (rb + 8) * LDS_ + k0);
            af[2] = packh2(Ad + rb * LDS_ + k0 + 8);
            af[3] = packh2(Ad + (rb + 8) * LDS_ + k0 + 8);
#pragma unroll
            for (int ni = 0; ni < 4; ++ni)
                mma_f16(acc[mi][ni], af, bf[ni]);
        }
    };

    // ---- pipelined mainloop: depth-3 prefetch over 4 buffers ----
    issue(0); issue(1); issue(2);
    for (int c = 0; c < NCHG; ++c) {
        if (c + 2 < NCHG) {
            asm volatile("cp.async.wait_group 2;" ::: "memory");
        } else if (c + 1 < NCHG) {
            asm volatile("cp.async.wait_group 1;" ::: "memory");
        } else {
            asm volatile("cp.async.wait_group 0;" ::: "memory");
        }
        __syncthreads();
        if (c + 3 < NCHG) issue(c + 3);
        compute(c & 3);
    }

    // ---- fill spatt (aliases ABUF(3); chunk 31 ran in buf 3, computes done) ----
    __syncthreads();
    float* spatt = dsm + SPATT_O;    // 96 floats: 64 rows + 2*FS halo
    if (tid < TILE_M + 2 * FS_) {
        int t = trow0 + tid - FS_;
        spatt[tid] = (t >= 0 && t < T_) ? prev_att[b * T_ + t] : 0.f;
    }
    __syncthreads();

    // ---- ext chunks (FIR taps + bias) into bufs 0,1,2 ----
    {
        const float4 z4 = make_float4(0.f, 0.f, 0.f, 0.f);
#pragma unroll
        for (int e = 0; e < 3; ++e) {
            float* Ad = dsm + ABUF(e);
            float* Bd = dsm + BBUF(e);
            float4 av, bv;
            // A rows: 64 (one per thread-row)
            if (e < 2) {
                const int kk = 16 * e + 4 * q;
                av = make_float4(spatt[r + kk], spatt[r + kk + 1],
                                 spatt[r + kk + 2], spatt[r + kk + 3]);
            } else {
                av = z4;
                if (q == 0) { av.x = spatt[r + 32]; av.y = 1.0f; }
            }
            *(float4*)(Ad + r * LDS_ + 4 * q) = av;
            // B rows: r and r+64
#pragma unroll
            for (int h = 0; h < 2; ++h) {
                const int rr = r + 64 * h;
                if (e < 2) {
                    const int kk = 16 * e + 4 * q;
                    bv = make_float4(g_eff[(kk + 0) * A_ + rr], g_eff[(kk + 1) * A_ + rr],
                                     g_eff[(kk + 2) * A_ + rr], g_eff[(kk + 3) * A_ + rr]);
                } else {
                    bv = z4;
                    if (q == 0) { bv.x = g_eff[32 * A_ + rr]; bv.y = g_pd[b * A_ + rr]; }
                }
                *(float4*)(Bd + rr * LDS_ + 4 * q) = bv;
            }
        }
    }
    __syncthreads();
    compute(0); compute(1); compute(2);
    __syncthreads();                 // sred aliases ABUF(0) below

    // ---- epilogue: tanh + out_w dot, reduce over a-dimension ----
    float* sred = dsm + SRED_O;      // [4][64]
    float ow0[4], ow1[4];
#pragma unroll
    for (int ni = 0; ni < 4; ++ni) {
        int c0 = warp_n * 32 + ni * 8 + 2 * tg;
        ow0[ni] = out_w[c0]; ow1[ni] = out_w[c0 + 1];
    }
#pragma unroll
    for (int mi = 0; mi < 2; ++mi) {
        float p0 = 0.f, p1 = 0.f;
#pragma unroll
        for (int ni = 0; ni < 4; ++ni) {
            p0 = fmaf(ow0[ni], tanhf(acc[mi][ni][0]), p0);
            p0 = fmaf(ow1[ni], tanhf(acc[mi][ni][1]), p0);
            p1 = fmaf(ow0[ni], tanhf(acc[mi][ni][2]), p1);
            p1 = fmaf(ow1[ni], tanhf(acc[mi][ni][3]), p1);
        }
        p0 += __shfl_down_sync(0xffffffffu, p0, 2, 4);
        p0 += __shfl_down_sync(0xffffffffu, p0, 1, 4);
        p1 += __shfl_down_sync(0xffffffffu, p1, 2, 4);
        p1 += __shfl_down_sync(0xffffffffu, p1, 1, 4);
        if (tg == 0) {
            int rb = warp_m * 32 + mi * 16 + g;
            sred[warp_n * TILE_M + rb] = p0;
            sred[warp_n * TILE_M + rb + 8] = p1;
        }
    }
    __syncthreads();

    if (tid < TILE_M) {
        int t = trow0 + tid;
        if (t < T_) {
            float s = sred[tid] + sred[TILE_M + tid] +
                      sred[2 * TILE_M + tid] + sred[3 * TILE_M + tid];
            g_score[b * T_ + t] = (t < len) ? s : -INFINITY;
        }
    }
}

// ---------------------------------------------------------------------------
// K2 (idx 2): per-batch softmax stats (max, 1/sum).  grid B_, 1024 threads.
// ---------------------------------------------------------------------------
__global__ void k_stats() {
    int b = blockIdx.x, tid = threadIdx.x;
    __shared__ float red[32];
    __shared__ float s_m;
    const float* sc = g_score + b * T_;

    float m = -INFINITY;
    for (int t = tid; t < T_; t += 1024) m = fmaxf(m, sc[t]);
#pragma unroll
    for (int o = 16; o; o >>= 1) m = fmaxf(m, __shfl_xor_sync(0xffffffffu, m, o));
    if ((tid & 31) == 0) red[tid >> 5] = m;
    __syncthreads();
    if (tid < 32) {
        float v = red[tid];
#pragma unroll
        for (int o = 16; o; o >>= 1) v = fmaxf(v, __shfl_xor_sync(0xffffffffu, v, o));
        if (tid == 0) s_m = v;
    }
    __syncthreads();
    m = s_m;

    float s = 0.f;
    for (int t = tid; t < T_; t += 1024) s += expf(sc[t] - m);
#pragma unroll
    for (int o = 16; o; o >>= 1) s += __shfl_xor_sync(0xffffffffu, s, o);
    if ((tid & 31) == 0) red[tid >> 5] = s;
    __syncthreads();
    if (tid < 32) {
        float v = red[tid];
#pragma unroll
        for (int o = 16; o; o >>= 1) v += __shfl_xor_sync(0xffffffffu, v, o);
        if (tid == 0) { g_stats[2 * b] = m; g_stats[2 * b + 1] = 1.f / v; }
    }
}

// ---------------------------------------------------------------------------
// K3 (idx 3): att-weight write + context accumulate.
//     grid (B_, SEG_), 512 threads = 4 row-groups x 128 d-lanes (float4).
// ---------------------------------------------------------------------------
__global__ void __launch_bounds__(512)
k_ctx(const float* __restrict__ enc, float* __restrict__ att_out,
      float* __restrict__ ctx_out, const int* __restrict__ lengths) {
    int b = blockIdx.x, seg = blockIdx.y, tid = threadIdx.x;
    __shared__ float w[TSEG];
    __shared__ float4 red4[3][128];
    const float m = g_stats[2 * b], inv = g_stats[2 * b + 1];
    const int t0 = seg * TSEG;
    if (tid < TSEG) {
        float sc = g_score[b * T_ + t0 + tid];
        float wv = expf(sc - m) * inv;       // exp(-inf)=0 handles the mask
        w[tid] = wv;
        att_out[b * T_ + t0 + tid] = wv;
    }
    __syncthreads();

    const int len = lengths[b];
    const int n = min(TSEG, max(0, len - t0));
    if (n <= 0) return;

    const int grp = tid >> 7;
    const int dl  = tid & 127;
    const float4* e = (const float4*)(enc + ((size_t)b * T_ + t0) * DE_) + dl;

    float4 acc = make_float4(0.f, 0.f, 0.f, 0.f);
#pragma unroll 4
    for (int tt = grp; tt < n; tt += 4) {
        float wv = w[tt];
        float4 v = e[(size_t)tt * (DE_ / 4)];
        acc.x = fmaf(wv, v.x, acc.x);
        acc.y = fmaf(wv, v.y, acc.y);
        acc.z = fmaf(wv, v.z, acc.z);
        acc.w = fmaf(wv, v.w, acc.w);
    }

    if (grp > 0) red4[grp - 1][dl] = acc;
    __syncthreads();
    if (grp == 0) {
#pragma unroll
        for (int j = 0; j < 3; ++j) {
            float4 v = red4[j][dl];
            acc.x += v.x; acc.y += v.y; acc.z += v.z; acc.w += v.w;
        }
        float* dst = ctx_out + b * DE_ + dl * 4;
        atomicAdd(dst + 0, acc.x);
        atomicAdd(dst + 1, acc.y);
        atomicAdd(dst + 2, acc.z);
        atomicAdd(dst + 3, acc.w);
    }
}

// ---------------------------------------------------------------------------
// Entry point
// ---------------------------------------------------------------------------
extern "C" void kernel_launch(void* const* d_in, const int* in_sizes, int n_in,
                              void* d_out, int out_size) {
    const float* input_enc   = (const float*)d_in[0];
    const int*   enc_lengths = (const int*)  d_in[1];
    const float* input_dec   = (const float*)d_in[2];
    const float* prev_att    = (const float*)d_in[3];
    const float* conv_w      = (const float*)d_in[4];
    const float* enc_w       = (const float*)d_in[5];
    const float* dec_w       = (const float*)d_in[6];
    const float* att_w       = (const float*)d_in[7];
    const float* att_b       = (const float*)d_in[8];
    const float* out_w       = (const float*)d_in[9];

    float* ctx_out = (float*)d_out;            // [B, DE]
    float* att_out = ctx_out + B_ * DE_;       // [B, T]

    static int attr_set = 0;
    if (!attr_set) {
        cudaFuncSetAttribute(k_score, cudaFuncAttributeMaxDynamicSharedMemorySize,
                             SMEM_FLOATS * 4);
        attr_set = 1;
    }

    k_prep<<<B_, 128>>>(att_w, conv_w, dec_w, input_dec, att_b, ctx_out);   // idx 0
    k_score<<<dim3((T_ + TILE_M - 1) / TILE_M, B_), 256, SMEM_FLOATS * 4>>>(
        input_enc, enc_w, prev_att, out_w, enc_lengths);                    // idx 1
    k_stats<<<B_, 1024>>>();                                                // idx 2
    k_ctx<<<dim3(B_, SEG_), 512>>>(input_enc, att_out, ctx_out, enc_lengths); // idx 3
}

// round 14
// speedup vs baseline: 1.1366x; 1.1366x over previous
#include <cuda_runtime.h>
#include <cuda_fp16.h>
#include <math.h>
#include <stdint.h>

// Problem constants
#define B_   32
#define T_   2000
#define DE_  512
#define DD_  1024
#define A_   128
#define FN_  32
#define FS_  16
#define KW_  33

#define TILE_M 128
#define BKF    16            // K floats per chunk (= one m16n8k16 slab)
#define NCHG   32            // gmem K-chunks (512/16)
#define LDS_   24            // A smem row stride (floats): conflict-free LDS.64
#define LDH_   24            // B smem row stride (halves): conflict-free LDS.32
#define SEG_   20
#define TSEG   (T_/SEG_)     // 100

// dynamic smem layout (float offsets):
//  4 A bufs (128x24 f32 = 3072 floats), 4 B bufs (128x24 f16 = 1536 floats),
//  spatt, ow, red
#define ABUF(i)  ((i) * 3072)
#define BBUF(i)  (12288 + (i) * 1536)     // as float offset; B is half*
#define SPATT_O  18432
#define SOW_O    18592
#define SRED_O   18720
#define SMEM_FLOATS 19232                 // 76928 bytes

// Scratch (no cudaMalloc allowed)
__device__ float  g_eff[KW_ * A_];        // eff[k][a]
__device__ float  g_pd[B_ * A_];          // dec projection + att_b
__device__ __half g_wh[A_ * DE_];         // enc_w pre-converted to fp16
__device__ float  g_score[B_ * T_];
__device__ float  g_stats[B_ * 2];        // max, 1/sum

__device__ __forceinline__ uint32_t smem_u32(const void* p) {
    uint32_t a;
    asm("{ .reg .u64 t; cvta.to.shared.u64 t, %1; cvt.u32.u64 %0, t; }" : "=r"(a) : "l"(p));
    return a;
}
__device__ __forceinline__ void cp16(uint32_t dst, uint64_t src, int srcsz) {
    asm volatile("cp.async.cg.shared.global [%0], [%1], 16, %2;"
                 :: "r"(dst), "l"(src), "r"(srcsz) : "memory");
}
// load two consecutive k floats, round to fp16 pair {lo=k, hi=k+1}
__device__ __forceinline__ uint32_t packh2(const float* p) {
    float2 v = *(const float2*)p;
    uint32_t r;
    asm("cvt.rn.f16x2.f32 %0, %1, %2;" : "=r"(r) : "f"(v.y), "f"(v.x));
    return r;
}
__device__ __forceinline__ void mma_f16(float* d, const uint32_t* a, const uint32_t* bb) {
    asm volatile(
        "mma.sync.aligned.m16n8k16.row.col.f32.f16.f16.f32 "
        "{%0,%1,%2,%3}, {%4,%5,%6,%7}, {%8,%9}, {%0,%1,%2,%3};"
        : "+f"(d[0]), "+f"(d[1]), "+f"(d[2]), "+f"(d[3])
        : "r"(a[0]), "r"(a[1]), "r"(a[2]), "r"(a[3]), "r"(bb[0]), "r"(bb[1]));
}

// ---------------------------------------------------------------------------
// K0 (idx 0): prep — eff fold (block 0), enc_w->fp16, zero ctx, dec projection.
//     grid B_, 256 threads.
// ---------------------------------------------------------------------------
__global__ void k_prep(const float* __restrict__ att_w, const float* __restrict__ conv_w,
                       const float* __restrict__ dec_w, const float* __restrict__ input_dec,
                       const float* __restrict__ att_b, const float* __restrict__ enc_w,
                       float* __restrict__ ctx_out) {
    __shared__ float sdec[DD_];
    __shared__ float sp[256];
    int b = blockIdx.x, tid = threadIdx.x;
    int gt = b * 256 + tid;                        // 8192 global threads

    // zero ctx accumulators (graph-replay safe)
    for (int i = gt; i < B_ * DE_; i += B_ * 256) ctx_out[i] = 0.f;

    // enc_w -> fp16 (65536 elems / 8192 threads = 8 each, float2->half2)
    for (int i = gt; i < A_ * DE_ / 2; i += B_ * 256) {
        float2 v = ((const float2*)enc_w)[i];
        ((__half2*)g_wh)[i] = __floats2half2_rn(v.x, v.y);
    }

    // block 0: eff[k][a] = sum_f att_w[a,f]*conv_w[f,k]   (threads 0..127)
    if (b == 0 && tid < A_) {
        int a = tid;
        float aw[FN_];
#pragma unroll
        for (int f = 0; f < FN_; ++f) aw[f] = att_w[a * FN_ + f];
        for (int k = 0; k < KW_; ++k) {
            float s = 0.f;
#pragma unroll
            for (int f = 0; f < FN_; ++f) s = fmaf(aw[f], conv_w[f * KW_ + k], s);
            g_eff[k * A_ + a] = s;
        }
    }

    // decoder projection: 2 threads per row (halves of DD_)
    for (int i = tid; i < DD_; i += blockDim.x) sdec[i] = input_dec[b * DD_ + i];
    __syncthreads();
    {
        const int row  = tid & 127;
        const int half = tid >> 7;                 // 0 or 1
        const float4* wr = (const float4*)(dec_w + (size_t)row * DD_ + half * (DD_ / 2));
        const float4* xr = (const float4*)(sdec + half * (DD_ / 2));
        float s = 0.f;
#pragma unroll 4
        for (int i = 0; i < DD_ / 8; ++i) {
            float4 w = wr[i], x = xr[i];
            s = fmaf(w.x, x.x, fmaf(w.y, x.y, fmaf(w.z, x.z, fmaf(w.w, x.w, s))));
        }
        sp[tid] = s;
        __syncthreads();
        if (tid < 128)
            g_pd[b * A_ + tid] = sp[tid] + sp[tid + 128] + att_b[tid];
    }
}

// ---------------------------------------------------------------------------
// K1 (idx 1): fp16 m16n8k16 mma.sync score GEMM (fp32 accum).
//     CTA tile 128x128, 8 warps (warp tile 64x32), occ 2.
//     A: fp32 cp.async; B: fp16 (pre-converted) cp.async, zero-cvt fragments.
// ---------------------------------------------------------------------------
__global__ void __launch_bounds__(256, 2)
k_score(const float* __restrict__ enc, const float* __restrict__ prev_att,
        const float* __restrict__ out_w, const int* __restrict__ lengths)
{
    extern __shared__ float dsm[];

    const int b     = blockIdx.y;
    const int trow0 = blockIdx.x * TILE_M;
    const int tid   = threadIdx.x;
    const int lane  = tid & 31;
    const int wid   = tid >> 5;
    const int warp_m = wid & 1;
    const int warp_n = wid >> 1;
    const int g     = lane >> 2;
    const int tg    = lane & 3;
    const int r     = tid >> 2;      // A loader row 0..63 (covers r, r+64)
    const int q     = tid & 3;       // A loader quad
    const int rb2   = tid >> 1;      // B loader row 0..127
    const int hb    = tid & 1;       // B loader 16B-half

    const int len = lengths[b];
    if (trow0 >= len) {              // fully masked tile
        for (int i = tid; i < TILE_M; i += 256) {
            int t = trow0 + i;
            if (t < T_) g_score[b * T_ + t] = -INFINITY;
        }
        return;
    }

    float* spatt = dsm + SPATT_O;
    float* s_ow  = dsm + SOW_O;
    float* sred  = dsm + SRED_O;

    for (int i = tid; i < TILE_M + 2 * FS_; i += 256) {
        int t = trow0 + i - FS_;
        spatt[i] = (t >= 0 && t < T_) ? prev_att[b * T_ + t] : 0.f;
    }
    if (tid < A_) s_ow[tid] = out_w[tid];

    const uint32_t sbase = smem_u32(dsm);
    uint64_t gA, gW;
    {
        const float* Abase = enc + ((size_t)b * T_ + trow0) * DE_;
        const __half* Wbase = g_wh;
        asm("cvta.to.global.u64 %0, %1;" : "=l"(gA) : "l"(Abase));
        asm("cvta.to.global.u64 %0, %1;" : "=l"(gW) : "l"(Wbase));
    }
    const int szA0 = (trow0 + r      < T_) ? 16 : 0;
    const int szA1 = (trow0 + r + 64 < T_) ? 16 : 0;
    const uint32_t soffA    = (uint32_t)(r * LDS_ + 4 * q) * 4u;
    const uint32_t rowskipA = 64u * LDS_ * 4u;
    const uint64_t goffA    = ((size_t)r * DE_ + 4 * q) * 4;
    const uint64_t growskpA = (size_t)64 * DE_ * 4;
    const uint32_t soffB    = (uint32_t)(rb2 * LDH_ * 2 + hb * 16);
    const uint64_t goffB    = ((size_t)rb2 * DE_ + hb * 8) * 2;

    auto issue = [&](int c) {
        const int bi = c & 3;
        const uint32_t da = sbase + (uint32_t)ABUF(bi) * 4u + soffA;
        const uint32_t db = sbase + (uint32_t)BBUF(bi) * 4u + soffB;
        const uint64_t offA = goffA + (uint64_t)c * (BKF * 4);
        const uint64_t offB = goffB + (uint64_t)c * (BKF * 2);
        cp16(da,            gA + offA,            szA0);
        cp16(da + rowskipA, gA + offA + growskpA, szA1);
        cp16(db,            gW + offB,            16);
        asm volatile("cp.async.commit_group;" ::: "memory");
    };

    float acc[4][4][4];
#pragma unroll
    for (int mi = 0; mi < 4; ++mi)
#pragma unroll
        for (int ni = 0; ni < 4; ++ni)
#pragma unroll
            for (int j = 0; j < 4; ++j) acc[mi][ni][j] = 0.f;

    auto compute = [&](int bi) {
        const float* Ad = dsm + ABUF(bi);
        const uint32_t Bd = sbase + (uint32_t)BBUF(bi) * 4u;
        const int k0 = 2 * tg;
        uint32_t bf[4][2];
#pragma unroll
        for (int ni = 0; ni < 4; ++ni) {
            int nb = warp_n * 32 + ni * 8 + g;
            uint32_t ba = Bd + (uint32_t)(nb * LDH_ + k0) * 2u;
            asm volatile("ld.shared.b32 %0, [%1];"      : "=r"(bf[ni][0]) : "r"(ba));
            asm volatile("ld.shared.b32 %0, [%1+16];"   : "=r"(bf[ni][1]) : "r"(ba));
        }
#pragma unroll
        for (int mi = 0; mi < 4; ++mi) {
            int rbw = warp_m * 64 + mi * 16 + g;
            uint32_t af[4];
            af[0] = packh2(Ad + rbw * LDS_ + k0);
            af[1] = packh2(Ad + (rbw + 8) * LDS_ + k0);
            af[2] = packh2(Ad + rbw * LDS_ + k0 + 8);
            af[3] = packh2(Ad + (rbw + 8) * LDS_ + k0 + 8);
#pragma unroll
            for (int ni = 0; ni < 4; ++ni)
                mma_f16(acc[mi][ni], af, bf[ni]);
        }
    };

    auto extsts = [&](int e, int bi) {
        float*  Ad = dsm + ABUF(bi);
        __half* Bd = (__half*)(dsm + BBUF(bi));
        const float4 z4 = make_float4(0.f, 0.f, 0.f, 0.f);
        // A rows r, r+64 (fp32)
#pragma unroll
        for (int h = 0; h < 2; ++h) {
            const int rr = r + 64 * h;
            float4 av;
            if (e < 2) {
                const int kk = 16 * e + 4 * q;
                av = make_float4(spatt[rr + kk], spatt[rr + kk + 1],
                                 spatt[rr + kk + 2], spatt[rr + kk + 3]);
            } else {
                av = z4;
                if (q == 0) { av.x = spatt[rr + 32]; av.y = 1.0f; }
            }
            *(float4*)(Ad + rr * LDS_ + 4 * q) = av;
        }
        // B row rb2 (fp16): thread writes halves [8*hb .. 8*hb+7] -> 4 half2
        {
            const int rr = rb2;
            const int kbase = 8 * hb;
            __half2* dst = (__half2*)(Bd + rr * LDH_ + kbase);
#pragma unroll
            for (int j = 0; j < 4; ++j) {
                int kk = kbase + 2 * j;
                float v0 = 0.f, v1 = 0.f;
                if (e < 2) {
                    v0 = g_eff[(16 * e + kk) * A_ + rr];
                    v1 = g_eff[(16 * e + kk + 1) * A_ + rr];
                } else if (kk == 0) {
                    v0 = g_eff[32 * A_ + rr];
                    v1 = g_pd[b * A_ + rr];
                }
                dst[j] = __floats2half2_rn(v0, v1);
            }
        }
    };

    // ---- pipelined mainloop: depth-3 prefetch over 4 buffers ----
    issue(0); issue(1); issue(2);
    for (int c = 0; c < NCHG; ++c) {
        if (c + 2 < NCHG) {
            asm volatile("cp.async.wait_group 2;" ::: "memory");
        } else if (c + 1 < NCHG) {
            asm volatile("cp.async.wait_group 1;" ::: "memory");
        } else {
            asm volatile("cp.async.wait_group 0;" ::: "memory");
        }
        __syncthreads();
        if (c + 3 < NCHG) issue(c + 3);
        compute(c & 3);
    }

    // ---- ext chunks in bufs 0,1,2 (chunk 31 computed on buf 3) ----
    extsts(0, 0); extsts(1, 1); extsts(2, 2);
    __syncthreads();
    compute(0); compute(1); compute(2);

    // ---- epilogue: tanh + out_w dot, reduce over a-dimension ----
    float ow0[4], ow1[4];
#pragma unroll
    for (int ni = 0; ni < 4; ++ni) {
        int c0 = warp_n * 32 + ni * 8 + 2 * tg;
        ow0[ni] = s_ow[c0]; ow1[ni] = s_ow[c0 + 1];
    }
#pragma unroll
    for (int mi = 0; mi < 4; ++mi) {
        float p0 = 0.f, p1 = 0.f;
#pragma unroll
        for (int ni = 0; ni < 4; ++ni) {
            p0 = fmaf(ow0[ni], tanhf(acc[mi][ni][0]), p0);
            p0 = fmaf(ow1[ni], tanhf(acc[mi][ni][1]), p0);
            p1 = fmaf(ow0[ni], tanhf(acc[mi][ni][2]), p1);
            p1 = fmaf(ow1[ni], tanhf(acc[mi][ni][3]), p1);
        }
        p0 += __shfl_down_sync(0xffffffffu, p0, 2, 4);
        p0 += __shfl_down_sync(0xffffffffu, p0, 1, 4);
        p1 += __shfl_down_sync(0xffffffffu, p1, 2, 4);
        p1 += __shfl_down_sync(0xffffffffu, p1, 1, 4);
        if (tg == 0) {
            int rbw = warp_m * 64 + mi * 16 + g;
            sred[warp_n * TILE_M + rbw] = p0;
            sred[warp_n * TILE_M + rbw + 8] = p1;
        }
    }
    __syncthreads();

    if (tid < TILE_M) {
        int t = trow0 + tid;
        if (t < T_) {
            float s = sred[tid] + sred[TILE_M + tid] +
                      sred[2 * TILE_M + tid] + sred[3 * TILE_M + tid];
            g_score[b * T_ + t] = (t < len) ? s : -INFINITY;
        }
    }
}

// ---------------------------------------------------------------------------
// K2 (idx 2): per-batch softmax stats (max, 1/sum).  grid B_, 1024 threads.
// ---------------------------------------------------------------------------
__global__ void k_stats() {
    int b = blockIdx.x, tid = threadIdx.x;
    __shared__ float red[32];
    __shared__ float s_m;
    const float* sc = g_score + b * T_;

    float m = -INFINITY;
    for (int t = tid; t < T_; t += 1024) m = fmaxf(m, sc[t]);
#pragma unroll
    for (int o = 16; o; o >>= 1) m = fmaxf(m, __shfl_xor_sync(0xffffffffu, m, o));
    if ((tid & 31) == 0) red[tid >> 5] = m;
    __syncthreads();
    if (tid < 32) {
        float v = red[tid];
#pragma unroll
        for (int o = 16; o; o >>= 1) v = fmaxf(v, __shfl_xor_sync(0xffffffffu, v, o));
        if (tid == 0) s_m = v;
    }
    __syncthreads();
    m = s_m;

    float s = 0.f;
    for (int t = tid; t < T_; t += 1024) s += expf(sc[t] - m);
#pragma unroll
    for (int o = 16; o; o >>= 1) s += __shfl_xor_sync(0xffffffffu, s, o);
    if ((tid & 31) == 0) red[tid >> 5] = s;
    __syncthreads();
    if (tid < 32) {
        float v = red[tid];
#pragma unroll
        for (int o = 16; o; o >>= 1) v += __shfl_xor_sync(0xffffffffu, v, o);
        if (tid == 0) { g_stats[2 * b] = m; g_stats[2 * b + 1] = 1.f / v; }
    }
}

// ---------------------------------------------------------------------------
// K3 (idx 3): att-weight write + context accumulate.
//     grid (B_, SEG_), 512 threads = 4 row-groups x 128 d-lanes (float4).
// ---------------------------------------------------------------------------
__global__ void __launch_bounds__(512)
k_ctx(const float* __restrict__ enc, float* __restrict__ att_out,
      float* __restrict__ ctx_out, const int* __restrict__ lengths) {
    int b = blockIdx.x, seg = blockIdx.y, tid = threadIdx.x;
    __shared__ float w[TSEG];
    __shared__ float4 red4[3][128];
    const float m = g_stats[2 * b], inv = g_stats[2 * b + 1];
    const int t0 = seg * TSEG;
    if (tid < TSEG) {
        float sc = g_score[b * T_ + t0 + tid];
        float wv = expf(sc - m) * inv;       // exp(-inf)=0 handles the mask
        w[tid] = wv;
        att_out[b * T_ + t0 + tid] = wv;
    }
    __syncthreads();

    const int len = lengths[b];
    const int n = min(TSEG, max(0, len - t0));
    if (n <= 0) return;

    const int grp = tid >> 7;
    const int dl  = tid & 127;
    const float4* e = (const float4*)(enc + ((size_t)b * T_ + t0) * DE_) + dl;

    float4 acc = make_float4(0.f, 0.f, 0.f, 0.f);
#pragma unroll 4
    for (int tt = grp; tt < n; tt += 4) {
        float wv = w[tt];
        float4 v = e[(size_t)tt * (DE_ / 4)];
        acc.x = fmaf(wv, v.x, acc.x);
        acc.y = fmaf(wv, v.y, acc.y);
        acc.z = fmaf(wv, v.z, acc.z);
        acc.w = fmaf(wv, v.w, acc.w);
    }

    if (grp > 0) red4[grp - 1][dl] = acc;
    __syncthreads();
    if (grp == 0) {
#pragma unroll
        for (int j = 0; j < 3; ++j) {
            float4 v = red4[j][dl];
            acc.x += v.x; acc.y += v.y; acc.z += v.z; acc.w += v.w;
        }
        float* dst = ctx_out + b * DE_ + dl * 4;
        atomicAdd(dst + 0, acc.x);
        atomicAdd(dst + 1, acc.y);
        atomicAdd(dst + 2, acc.z);
        atomicAdd(dst + 3, acc.w);
    }
}

// ---------------------------------------------------------------------------
// Entry point
// ---------------------------------------------------------------------------
extern "C" void kernel_launch(void* const* d_in, const int* in_sizes, int n_in,
                              void* d_out, int out_size) {
    const float* input_enc   = (const float*)d_in[0];
    const int*   enc_lengths = (const int*)  d_in[1];
    const float* input_dec   = (const float*)d_in[2];
    const float* prev_att    = (const float*)d_in[3];
    const float* conv_w      = (const float*)d_in[4];
    const float* enc_w       = (const float*)d_in[5];
    const float* dec_w       = (const float*)d_in[6];
    const float* att_w       = (const float*)d_in[7];
    const float* att_b       = (const float*)d_in[8];
    const float* out_w       = (const float*)d_in[9];

    float* ctx_out = (float*)d_out;            // [B, DE]
    float* att_out = ctx_out + B_ * DE_;       // [B, T]

    static int attr_set = 0;
    if (!attr_set) {
        cudaFuncSetAttribute(k_score, cudaFuncAttributeMaxDynamicSharedMemorySize,
                             SMEM_FLOATS * 4);
        attr_set = 1;
    }

    k_prep<<<B_, 256>>>(att_w, conv_w, dec_w, input_dec, att_b, enc_w, ctx_out); // idx 0
    k_score<<<dim3((T_ + TILE_M - 1) / TILE_M, B_), 256, SMEM_FLOATS * 4>>>(
        input_enc, prev_att, out_w, enc_lengths);                                // idx 1
    k_stats<<<B_, 1024>>>();                                                     // idx 2
    k_ctx<<<dim3(B_, SEG_), 512>>>(input_enc, att_out, ctx_out, enc_lengths);    // idx 3
}